// round 14
// baseline (speedup 1.0000x reference)
#include <cuda_runtime.h>
#include <cuda_fp16.h>
#include <cstdint>

#define N_NODES 50000
#define N_EDGES 800000
#define D 128
#define NT 391            // ceil(N_NODES/128)
#define SCAN_BLOCKS 196   // 196*256 = 50176 >= N_NODES

// ==================== scratch (no allocations allowed) ====================
// zeroed with ONE memset per call
__device__ struct ZeroRegion {
    int hist[N_NODES];
    unsigned long long state[SCAN_BLOCKS];   // lookback: status(2b)<<62 | value
} g_z;
__device__ int g_cursor[N_NODES];
__device__ int g_rowstart[N_NODES + 1];
__device__ int g_col[N_EDGES];
// fp16 swizzled weight images: [matrix 0..5][2 kchunks x 128 x 64]
__device__ __align__(128) __half g_Wimg[6][D * D];
// fp16 swizzled h tile images (ping-pong sets)
__device__ __align__(128) __half g_img[2][(size_t)NT * 16384];
// fp16 swizzled hneigh tile image
__device__ __align__(128) __half g_imgN[(size_t)NT * 16384];

// XOR swizzle: row-major 64 fp16 per row (128B), 8 chunks of 16B, chunk ^= row&7
__device__ __forceinline__ uint32_t swz(uint32_t row, uint32_t kbyte) {
    return row * 128u + ((((kbyte >> 4) ^ (row & 7u)) << 4) | (kbyte & 15u));
}

__device__ __forceinline__ uint32_t smem_u32(const void* p) {
    uint32_t a;
    asm("{ .reg .u64 t; cvta.to.shared.u64 t, %1; cvt.u32.u64 %0, t; }" : "=r"(a) : "l"(p));
    return a;
}
__device__ __forceinline__ void cp_async16(uint32_t saddr, const void* gptr) {
    asm volatile("cp.async.cg.shared.global [%0], [%1], 16;" :: "r"(saddr), "l"(gptr));
}
#define CP_COMMIT() asm volatile("cp.async.commit_group;" ::: "memory")
#define CP_WAIT(n)  asm volatile("cp.async.wait_group %0;" :: "n"(n) : "memory")

__device__ __forceinline__ void ldsm_x4(uint32_t addr, uint32_t& r0, uint32_t& r1,
                                        uint32_t& r2, uint32_t& r3) {
    asm volatile("ldmatrix.sync.aligned.m8n8.x4.shared.b16 {%0,%1,%2,%3}, [%4];"
                 : "=r"(r0), "=r"(r1), "=r"(r2), "=r"(r3) : "r"(addr));
}
__device__ __forceinline__ void mma_16816(float* c, const uint32_t* a, const uint32_t* b) {
    asm volatile(
        "mma.sync.aligned.m16n8k16.row.col.f32.f16.f16.f32 "
        "{%0,%1,%2,%3}, {%4,%5,%6,%7}, {%8,%9}, {%0,%1,%2,%3};"
        : "+f"(c[0]), "+f"(c[1]), "+f"(c[2]), "+f"(c[3])
        : "r"(a[0]), "r"(a[1]), "r"(a[2]), "r"(a[3]), "r"(b[0]), "r"(b[1]));
}
// 4 packed halves -> 4 floats
__device__ __forceinline__ float4 h4_to_f4(uint2 u) {
    __half2 a = *reinterpret_cast<__half2*>(&u.x);
    __half2 b = *reinterpret_cast<__half2*>(&u.y);
    float2 fa = __half22float2(a);
    float2 fb = __half22float2(b);
    return make_float4(fa.x, fa.y, fb.x, fb.y);
}
__device__ __forceinline__ uint32_t pack_h2(float x, float y) {
    __half2 h = __floats2half2_rn(x, y);
    return *reinterpret_cast<uint32_t*>(&h);
}

// ==================== CSR build ====================
__global__ void hist_kernel(const int4* __restrict__ dst4) {
    int i = blockIdx.x * blockDim.x + threadIdx.x;
    if (i < N_EDGES / 4) {
        int4 d = dst4[i];
        atomicAdd(&g_z.hist[d.x], 1);
        atomicAdd(&g_z.hist[d.y], 1);
        atomicAdd(&g_z.hist[d.z], 1);
        atomicAdd(&g_z.hist[d.w], 1);
    }
}

// single-pass decoupled-lookback scan: hist -> rowstart/cursor (+ total)
__global__ void scan_lookback() {
    __shared__ int sh[256];
    __shared__ int s_prefix;
    int t = threadIdx.x;
    int bid = blockIdx.x;
    int idx = bid * 256 + t;
    int v = (idx < N_NODES) ? g_z.hist[idx] : 0;
    sh[t] = v;
    __syncthreads();
    #pragma unroll
    for (int off = 1; off < 256; off <<= 1) {
        int x = sh[t];
        int add = (t >= off) ? sh[t - off] : 0;
        __syncthreads();
        sh[t] = x + add;
        __syncthreads();
    }
    int incl = sh[t];

    // publish aggregate (or prefix for block 0)
    if (t == 255) {
        unsigned long long val = ((bid == 0) ? (2ULL << 62) : (1ULL << 62))
                               | (unsigned long long)(unsigned)sh[255];
        __threadfence();
        atomicExch((unsigned long long*)&g_z.state[bid], val);
    }
    // lookback (thread 0)
    if (t == 0) {
        int prefix = 0;
        int look = bid - 1;
        while (look >= 0) {
            unsigned long long s = *((volatile unsigned long long*)&g_z.state[look]);
            unsigned status = (unsigned)(s >> 62);
            if (status == 0) continue;           // spin
            prefix += (int)(unsigned)(s & 0xFFFFFFFFULL);
            if (status == 2u) break;             // found inclusive prefix
            --look;
        }
        s_prefix = prefix;
        if (bid > 0) {
            unsigned long long val = (2ULL << 62)
                                   | (unsigned long long)(unsigned)(prefix + sh[255]);
            __threadfence();
            atomicExch((unsigned long long*)&g_z.state[bid], val);
        }
    }
    __syncthreads();
    int ex = s_prefix + incl - v;                // global exclusive
    if (idx < N_NODES) {
        g_rowstart[idx] = ex;
        g_cursor[idx] = ex;
    }
    if (bid == SCAN_BLOCKS - 1 && t == 255)
        g_rowstart[N_NODES] = s_prefix + sh[255];
}

__global__ void fill_kernel(const int4* __restrict__ src4, const int4* __restrict__ dst4) {
    int i = blockIdx.x * blockDim.x + threadIdx.x;
    if (i < N_EDGES / 4) {
        int4 s = src4[i];
        int4 d = dst4[i];
        int p0 = atomicAdd(&g_cursor[d.x], 1);
        int p1 = atomicAdd(&g_cursor[d.y], 1);
        int p2 = atomicAdd(&g_cursor[d.z], 1);
        int p3 = atomicAdd(&g_cursor[d.w], 1);
        g_col[p0] = s.x;
        g_col[p1] = s.y;
        g_col[p2] = s.z;
        g_col[p3] = s.w;
    }
}

// ==================== merged: features->img0 (blocks < NT) + weight prep ==========
__global__ void convert_prep(const float* __restrict__ h, char* __restrict__ img,
                             const float* W0s, const float* W0n, const float* W1s,
                             const float* W1n, const float* W2s, const float* W2n) {
    if (blockIdx.x < NT) {
        int tile = blockIdx.x;
        int m0 = tile * 128;
        #pragma unroll 4
        for (int it = 0; it < 32; ++it) {
            int idx = threadIdx.x + it * 256;   // (row, kpair)
            int row = idx >> 6;
            int k = (idx & 63) * 2;
            int gm = m0 + row;
            float2 a = (gm < N_NODES) ? *reinterpret_cast<const float2*>(h + (size_t)gm * D + k)
                                      : make_float2(0.f, 0.f);
            uint32_t off = (uint32_t)tile * 32768u + (uint32_t)(k >> 6) * 16384u
                         + swz((uint32_t)row, (uint32_t)((k & 63) * 2));
            *(uint32_t*)(img + off) = pack_h2(a.x, a.y);
        }
    } else {
        const float* Wp[6] = {W0s, W0n, W1s, W1n, W2s, W2n};
        int b = blockIdx.x - NT;      // 0..47
        int mat = b >> 3;
        int sub = b & 7;
        const float* W = Wp[mat];
        char* wimg = (char*)g_Wimg[mat];
        for (int t = threadIdx.x; t < 1024; t += blockDim.x) {
            int idx = sub * 1024 + t;
            int n = idx >> 6;
            int k = (idx & 63) * 2;
            float a0 = W[(size_t)k * D + n];
            float a1 = W[(size_t)(k + 1) * D + n];
            uint32_t off = (uint32_t)(k >> 6) * 16384u
                         + swz((uint32_t)n, (uint32_t)((k & 63) * 2));
            *(uint32_t*)(wimg + off) = pack_h2(a0, a1);
        }
    }
}

// ==================== aggregation: warp/node, 8 edges in flight ====================
__global__ void aggregate_kernel(const char* __restrict__ img, char* __restrict__ nimg) {
    int node = (blockIdx.x * blockDim.x + threadIdx.x) >> 5;
    int lane = threadIdx.x & 31;
    if (node >= N_NODES) return;
    int beg = g_rowstart[node];
    int end = g_rowstart[node + 1];

    const int k0 = lane * 4;                                  // features k0..k0+3
    const uint32_t laneoff = (uint32_t)(k0 >> 6) * 16384u;    // k-chunk select
    const uint32_t kb = (uint32_t)((k0 & 63) * 2);            // byte within row

    auto addr = [&](int s) {
        return (uint32_t)(s >> 7) * 32768u + laneoff + swz((uint32_t)(s & 127), kb);
    };

    float4 acc = make_float4(0.f, 0.f, 0.f, 0.f);
    int i = beg;
    for (; i + 8 <= end; i += 8) {
        uint2 u[8];
        #pragma unroll
        for (int e = 0; e < 8; ++e)
            u[e] = *(const uint2*)(img + addr(g_col[i + e]));
        #pragma unroll
        for (int e = 0; e < 8; ++e) {
            float4 v = h4_to_f4(u[e]);
            acc.x += v.x; acc.y += v.y; acc.z += v.z; acc.w += v.w;
        }
    }
    for (; i + 4 <= end; i += 4) {
        uint2 u[4];
        #pragma unroll
        for (int e = 0; e < 4; ++e)
            u[e] = *(const uint2*)(img + addr(g_col[i + e]));
        #pragma unroll
        for (int e = 0; e < 4; ++e) {
            float4 v = h4_to_f4(u[e]);
            acc.x += v.x; acc.y += v.y; acc.z += v.z; acc.w += v.w;
        }
    }
    for (; i < end; ++i) {
        float4 v = h4_to_f4(*(const uint2*)(img + addr(g_col[i])));
        acc.x += v.x; acc.y += v.y; acc.z += v.z; acc.w += v.w;
    }
    float sc = 1.0f / fmaxf((float)(end - beg), 1.0f);

    int tile = node >> 7;
    int row = node & 127;
    uint32_t off = (uint32_t)tile * 32768u + laneoff + swz((uint32_t)row, kb);
    uint2 o2v;
    o2v.x = pack_h2(acc.x * sc, acc.y * sc);
    o2v.y = pack_h2(acc.z * sc, acc.w * sc);
    *(uint2*)(nimg + off) = o2v;
}

// ==================== HMMA dual GEMM, fp16 single-pass, 4x32KB phases ==============
__global__ void __launch_bounds__(256, 2)
gemm_hmma_kernel(const char* __restrict__ imgA, const char* __restrict__ imgN,
                 const char* __restrict__ Bs, const char* __restrict__ Bn,
                 const float* __restrict__ bias, float* __restrict__ out,
                 char* __restrict__ oImg, int relu, int write_img) {
    extern __shared__ char dyn_smem[];
    uint32_t sbase = (smem_u32(dyn_smem) + 127u) & ~127u;

    const int tid = threadIdx.x;
    const int wid = tid >> 5;
    const int lane = tid & 31;
    const int tile = blockIdx.x;
    const int m0 = tile * 128;
    const int wm = (wid >> 2) * 64;
    const int wn = (wid & 3) * 32;

    // 4 phases: p = part*2 + kc
    const char* srcA[4];
    const char* srcB[4];
    {
        const char* A0 = imgA + (size_t)tile * 32768;
        const char* N0 = imgN + (size_t)tile * 32768;
        #pragma unroll
        for (int kc = 0; kc < 2; ++kc) {
            srcA[kc] = A0 + kc * 16384;      srcB[kc] = Bs + kc * 16384;
            srcA[2 + kc] = N0 + kc * 16384;  srcB[2 + kc] = Bn + kc * 16384;
        }
    }

    auto stage = [&](int p, int b) {
        uint32_t sb = sbase + (uint32_t)b * 32768u;
        #pragma unroll
        for (int i = 0; i < 4; ++i) {
            uint32_t o = (uint32_t)(tid + i * 256) * 16u;
            cp_async16(sb + o, srcA[p] + o);
            cp_async16(sb + 16384 + o, srcB[p] + o);
        }
        CP_COMMIT();
    };

    float acc[4][4][4];
    #pragma unroll
    for (int i = 0; i < 4; i++)
        #pragma unroll
        for (int j = 0; j < 4; j++)
            #pragma unroll
            for (int r = 0; r < 4; r++) acc[i][j][r] = 0.f;

    stage(0, 0);

    #pragma unroll 1
    for (int p = 0; p < 4; ++p) {
        if (p < 3) { stage(p + 1, (p + 1) & 1); CP_WAIT(1); }
        else       { CP_WAIT(0); }
        __syncthreads();

        uint32_t sb = sbase + (uint32_t)(p & 1) * 32768u;
        const uint32_t sA = sb, sB = sb + 16384;
        #pragma unroll
        for (int ks = 0; ks < 4; ++ks) {
            uint32_t a[4][4];
            #pragma unroll
            for (int i = 0; i < 4; ++i) {
                uint32_t row = wm + i * 16 + (lane & 15);
                uint32_t kbyte = ks * 32 + ((lane >> 4) << 4);
                ldsm_x4(sA + swz(row, kbyte), a[i][0], a[i][1], a[i][2], a[i][3]);
            }
            uint32_t b[4][2];
            #pragma unroll
            for (int jj = 0; jj < 2; ++jj) {
                uint32_t mi = (uint32_t)lane >> 3;
                uint32_t row = wn + jj * 16 + ((mi >> 1) << 3) + (lane & 7);
                uint32_t kbyte = ks * 32 + ((mi & 1) << 4);
                uint32_t r0, r1, r2, r3;
                ldsm_x4(sB + swz(row, kbyte), r0, r1, r2, r3);
                b[jj * 2 + 0][0] = r0; b[jj * 2 + 0][1] = r1;
                b[jj * 2 + 1][0] = r2; b[jj * 2 + 1][1] = r3;
            }
            #pragma unroll
            for (int i = 0; i < 4; ++i)
                #pragma unroll
                for (int j = 0; j < 4; ++j)
                    mma_16816(acc[i][j], a[i], b[j]);
        }
        __syncthreads();   // all warps done reading buf before restage
    }

    // ---- epilogue: bias + relu; fp16 next-layer image OR final fp32 out ----
    #pragma unroll
    for (int i = 0; i < 4; ++i) {
        int rloc0 = wm + i * 16 + (lane >> 2);
        int r0 = m0 + rloc0;
        #pragma unroll
        for (int j = 0; j < 4; ++j) {
            int col = wn + j * 8 + (lane & 3) * 2;
            float bx = bias[col], by = bias[col + 1];
            float2 v0 = make_float2(acc[i][j][0] + bx, acc[i][j][1] + by);
            float2 v1 = make_float2(acc[i][j][2] + bx, acc[i][j][3] + by);
            if (relu) {
                v0.x = fmaxf(v0.x, 0.f); v0.y = fmaxf(v0.y, 0.f);
                v1.x = fmaxf(v1.x, 0.f); v1.y = fmaxf(v1.y, 0.f);
            }
            if (write_img) {
                uint32_t obase = (uint32_t)tile * 32768u + (uint32_t)(col >> 6) * 16384u;
                uint32_t kb = (uint32_t)((col & 63) * 2);
                if (r0 < N_NODES)
                    *(uint32_t*)(oImg + obase + swz((uint32_t)rloc0, kb)) = pack_h2(v0.x, v0.y);
                if (r0 + 8 < N_NODES)
                    *(uint32_t*)(oImg + obase + swz((uint32_t)(rloc0 + 8), kb)) = pack_h2(v1.x, v1.y);
            } else {
                if (r0 < N_NODES)
                    *reinterpret_cast<float2*>(out + (size_t)r0 * D + col) = v0;
                if (r0 + 8 < N_NODES)
                    *reinterpret_cast<float2*>(out + (size_t)(r0 + 8) * D + col) = v1;
            }
        }
    }
}

// ==================== launch ====================
extern "C" void kernel_launch(void* const* d_in, const int* in_sizes, int n_in,
                              void* d_out, int out_size) {
    const float* features = (const float*)d_in[0];
    const int* src = (const int*)d_in[1];
    const int* dst = (const int*)d_in[2];
    const float* Ws[3] = {(const float*)d_in[3], (const float*)d_in[6], (const float*)d_in[9]};
    const float* Wn[3] = {(const float*)d_in[4], (const float*)d_in[7], (const float*)d_in[10]};
    const float* bb[3] = {(const float*)d_in[5], (const float*)d_in[8], (const float*)d_in[11]};
    float* out = (float*)d_out;

    void *p_z, *p_img, *p_imgN;
    cudaGetSymbolAddress(&p_z, g_z);
    cudaGetSymbolAddress(&p_img, g_img);
    cudaGetSymbolAddress(&p_imgN, g_imgN);

    const size_t ISZ = (size_t)NT * 32768;   // bytes per h image
    char* himg = (char*)p_img;
    auto himgp = [&](int set) { return himg + (size_t)set * ISZ; };
    char* nimg = (char*)p_imgN;
    // weight images accessed via device symbol inside convert_prep; gemm needs raw ptrs:
    void* p_wimg;
    cudaGetSymbolAddress(&p_wimg, g_Wimg);
    char* wimg = (char*)p_wimg;
    auto wimgp = [&](int mat) { return wimg + (size_t)mat * 32768; };

    const size_t smem_bytes = 2 * 32768 + 128;
    cudaFuncSetAttribute(gemm_hmma_kernel, cudaFuncAttributeMaxDynamicSharedMemorySize,
                         (int)smem_bytes);

    cudaMemsetAsync(p_z, 0, sizeof(ZeroRegion));
    hist_kernel<<<(N_EDGES / 4 + 255) / 256, 256>>>((const int4*)dst);
    convert_prep<<<NT + 48, 256>>>(features, himgp(0),
                                   Ws[0], Wn[0], Ws[1], Wn[1], Ws[2], Wn[2]);
    scan_lookback<<<SCAN_BLOCKS, 256>>>();
    fill_kernel<<<(N_EDGES / 4 + 255) / 256, 256>>>((const int4*)src, (const int4*)dst);

    for (int l = 0; l < 3; ++l) {
        int rset = l & 1;            // 0,1,0
        int wset = 1 - rset;
        aggregate_kernel<<<(N_NODES * 32 + 255) / 256, 256>>>(himgp(rset), nimg);
        gemm_hmma_kernel<<<NT, 256, smem_bytes>>>(
            himgp(rset), nimg, wimgp(l * 2 + 0), wimgp(l * 2 + 1),
            bb[l], out, himgp(wset), (l < 2) ? 1 : 0, (l < 2) ? 1 : 0);
    }
}

// round 15
// speedup vs baseline: 1.0552x; 1.0552x over previous
#include <cuda_runtime.h>
#include <cuda_fp16.h>
#include <cstdint>

#define N_NODES 50000
#define N_EDGES 800000
#define D 128
#define NT 391            // ceil(N_NODES/128)
#define SCAN_BLOCKS 196   // 196*256 = 50176 >= N_NODES

// ==================== scratch (no allocations allowed) ====================
__device__ int g_hist[N_NODES];
__device__ int g_rank[N_EDGES];
__device__ int g_rowstart[N_NODES + 1];
__device__ int g_col[N_EDGES];
__device__ int g_blocksum[SCAN_BLOCKS];
__device__ int g_blockoff[SCAN_BLOCKS];
// fp16 swizzled weight images: [matrix 0..5][2 kchunks x 128 x 64]
__device__ __align__(128) __half g_Wimg[6][D * D];
// fp16 swizzled h tile images (ping-pong sets)
__device__ __align__(128) __half g_img[2][(size_t)NT * 16384];
// fp16 swizzled hneigh tile image
__device__ __align__(128) __half g_imgN[(size_t)NT * 16384];

// XOR swizzle: row-major 64 fp16 per row (128B), 8 chunks of 16B, chunk ^= row&7
__device__ __forceinline__ uint32_t swz(uint32_t row, uint32_t kbyte) {
    return row * 128u + ((((kbyte >> 4) ^ (row & 7u)) << 4) | (kbyte & 15u));
}

__device__ __forceinline__ uint32_t smem_u32(const void* p) {
    uint32_t a;
    asm("{ .reg .u64 t; cvta.to.shared.u64 t, %1; cvt.u32.u64 %0, t; }" : "=r"(a) : "l"(p));
    return a;
}
__device__ __forceinline__ void cp_async16(uint32_t saddr, const void* gptr) {
    asm volatile("cp.async.cg.shared.global [%0], [%1], 16;" :: "r"(saddr), "l"(gptr));
}
#define CP_COMMIT() asm volatile("cp.async.commit_group;" ::: "memory")
#define CP_WAIT(n)  asm volatile("cp.async.wait_group %0;" :: "n"(n) : "memory")

__device__ __forceinline__ void ldsm_x4(uint32_t addr, uint32_t& r0, uint32_t& r1,
                                        uint32_t& r2, uint32_t& r3) {
    asm volatile("ldmatrix.sync.aligned.m8n8.x4.shared.b16 {%0,%1,%2,%3}, [%4];"
                 : "=r"(r0), "=r"(r1), "=r"(r2), "=r"(r3) : "r"(addr));
}
__device__ __forceinline__ void mma_16816(float* c, const uint32_t* a, const uint32_t* b) {
    asm volatile(
        "mma.sync.aligned.m16n8k16.row.col.f32.f16.f16.f32 "
        "{%0,%1,%2,%3}, {%4,%5,%6,%7}, {%8,%9}, {%0,%1,%2,%3};"
        : "+f"(c[0]), "+f"(c[1]), "+f"(c[2]), "+f"(c[3])
        : "r"(a[0]), "r"(a[1]), "r"(a[2]), "r"(a[3]), "r"(b[0]), "r"(b[1]));
}
// 4 packed halves -> 4 floats
__device__ __forceinline__ float4 h4_to_f4(uint2 u) {
    __half2 a = *reinterpret_cast<__half2*>(&u.x);
    __half2 b = *reinterpret_cast<__half2*>(&u.y);
    float2 fa = __half22float2(a);
    float2 fb = __half22float2(b);
    return make_float4(fa.x, fa.y, fb.x, fb.y);
}
__device__ __forceinline__ uint32_t pack_h2(float x, float y) {
    __half2 h = __floats2half2_rn(x, y);
    return *reinterpret_cast<uint32_t*>(&h);
}

// ==================== CSR build ====================
// hist + per-edge rank (rank = return of atomicAdd)
__global__ void hist_kernel(const int4* __restrict__ dst4, int4* __restrict__ rank4) {
    int i = blockIdx.x * blockDim.x + threadIdx.x;
    if (i < N_EDGES / 4) {
        int4 d = dst4[i];
        int4 r;
        r.x = atomicAdd(&g_hist[d.x], 1);
        r.y = atomicAdd(&g_hist[d.y], 1);
        r.z = atomicAdd(&g_hist[d.z], 1);
        r.w = atomicAdd(&g_hist[d.w], 1);
        rank4[i] = r;
    }
}

__global__ void scan_local() {
    __shared__ int sh[256];
    int t = threadIdx.x;
    int idx = blockIdx.x * 256 + t;
    int v = (idx < N_NODES) ? g_hist[idx] : 0;
    sh[t] = v;
    __syncthreads();
    #pragma unroll
    for (int off = 1; off < 256; off <<= 1) {
        int x = sh[t];
        int add = (t >= off) ? sh[t - off] : 0;
        __syncthreads();
        sh[t] = x + add;
        __syncthreads();
    }
    if (idx < N_NODES) g_rowstart[idx] = sh[t] - v;
    if (t == 255) g_blocksum[blockIdx.x] = sh[255];
}

__global__ void scan_blocks() {
    __shared__ int sh[256];
    int t = threadIdx.x;
    int v = (t < SCAN_BLOCKS) ? g_blocksum[t] : 0;
    sh[t] = v;
    __syncthreads();
    #pragma unroll
    for (int off = 1; off < 256; off <<= 1) {
        int x = sh[t];
        int add = (t >= off) ? sh[t - off] : 0;
        __syncthreads();
        sh[t] = x + add;
        __syncthreads();
    }
    if (t < SCAN_BLOCKS) g_blockoff[t] = sh[t] - v;
    if (t == 255) g_rowstart[N_NODES] = sh[255];
}

__global__ void scan_apply() {
    int idx = blockIdx.x * 256 + threadIdx.x;
    if (idx < N_NODES)
        g_rowstart[idx] += g_blockoff[blockIdx.x];
}

// atomic-free fill: pos = rowstart[dst] + rank
__global__ void fill_kernel(const int4* __restrict__ src4, const int4* __restrict__ dst4,
                            const int4* __restrict__ rank4) {
    int i = blockIdx.x * blockDim.x + threadIdx.x;
    if (i < N_EDGES / 4) {
        int4 s = src4[i];
        int4 d = dst4[i];
        int4 r = rank4[i];
        g_col[g_rowstart[d.x] + r.x] = s.x;
        g_col[g_rowstart[d.y] + r.y] = s.y;
        g_col[g_rowstart[d.z] + r.z] = s.z;
        g_col[g_rowstart[d.w] + r.w] = s.w;
    }
}

// ==================== merged: features->img0 (blocks < NT) + weight prep ==========
__global__ void convert_prep(const float* __restrict__ h, char* __restrict__ img,
                             const float* W0s, const float* W0n, const float* W1s,
                             const float* W1n, const float* W2s, const float* W2n) {
    if (blockIdx.x < NT) {
        int tile = blockIdx.x;
        int m0 = tile * 128;
        #pragma unroll 4
        for (int it = 0; it < 32; ++it) {
            int idx = threadIdx.x + it * 256;   // (row, kpair)
            int row = idx >> 6;
            int k = (idx & 63) * 2;
            int gm = m0 + row;
            float2 a = (gm < N_NODES) ? *reinterpret_cast<const float2*>(h + (size_t)gm * D + k)
                                      : make_float2(0.f, 0.f);
            uint32_t off = (uint32_t)tile * 32768u + (uint32_t)(k >> 6) * 16384u
                         + swz((uint32_t)row, (uint32_t)((k & 63) * 2));
            *(uint32_t*)(img + off) = pack_h2(a.x, a.y);
        }
    } else {
        const float* Wp[6] = {W0s, W0n, W1s, W1n, W2s, W2n};
        int b = blockIdx.x - NT;      // 0..47
        int mat = b >> 3;
        int sub = b & 7;
        const float* W = Wp[mat];
        char* wimg = (char*)g_Wimg[mat];
        for (int t = threadIdx.x; t < 1024; t += blockDim.x) {
            int idx = sub * 1024 + t;
            int n = idx >> 6;
            int k = (idx & 63) * 2;
            float a0 = W[(size_t)k * D + n];
            float a1 = W[(size_t)(k + 1) * D + n];
            uint32_t off = (uint32_t)(k >> 6) * 16384u
                         + swz((uint32_t)n, (uint32_t)((k & 63) * 2));
            *(uint32_t*)(wimg + off) = pack_h2(a0, a1);
        }
    }
}

// ==================== aggregation: warp/node, gathers fp16 image -> fp16 image =====
__global__ void aggregate_kernel(const char* __restrict__ img, char* __restrict__ nimg) {
    int node = (blockIdx.x * blockDim.x + threadIdx.x) >> 5;
    int lane = threadIdx.x & 31;
    if (node >= N_NODES) return;
    int beg = g_rowstart[node];
    int end = g_rowstart[node + 1];

    const int k0 = lane * 4;                                  // features k0..k0+3
    const uint32_t laneoff = (uint32_t)(k0 >> 6) * 16384u;    // k-chunk select
    const uint32_t kb = (uint32_t)((k0 & 63) * 2);            // byte within row

    float4 acc = make_float4(0.f, 0.f, 0.f, 0.f);
    int i = beg;
    for (; i + 4 <= end; i += 4) {
        int s0 = g_col[i + 0];
        int s1 = g_col[i + 1];
        int s2 = g_col[i + 2];
        int s3 = g_col[i + 3];
        uint32_t o0 = (uint32_t)(s0 >> 7) * 32768u + laneoff + swz((uint32_t)(s0 & 127), kb);
        uint32_t o1 = (uint32_t)(s1 >> 7) * 32768u + laneoff + swz((uint32_t)(s1 & 127), kb);
        uint32_t o2 = (uint32_t)(s2 >> 7) * 32768u + laneoff + swz((uint32_t)(s2 & 127), kb);
        uint32_t o3 = (uint32_t)(s3 >> 7) * 32768u + laneoff + swz((uint32_t)(s3 & 127), kb);
        float4 v0 = h4_to_f4(*(const uint2*)(img + o0));
        float4 v1 = h4_to_f4(*(const uint2*)(img + o1));
        float4 v2 = h4_to_f4(*(const uint2*)(img + o2));
        float4 v3 = h4_to_f4(*(const uint2*)(img + o3));
        acc.x += (v0.x + v1.x) + (v2.x + v3.x);
        acc.y += (v0.y + v1.y) + (v2.y + v3.y);
        acc.z += (v0.z + v1.z) + (v2.z + v3.z);
        acc.w += (v0.w + v1.w) + (v2.w + v3.w);
    }
    for (; i < end; ++i) {
        int s = g_col[i];
        uint32_t o = (uint32_t)(s >> 7) * 32768u + laneoff + swz((uint32_t)(s & 127), kb);
        float4 v = h4_to_f4(*(const uint2*)(img + o));
        acc.x += v.x; acc.y += v.y; acc.z += v.z; acc.w += v.w;
    }
    float sc = 1.0f / fmaxf((float)(end - beg), 1.0f);

    int tile = node >> 7;
    int row = node & 127;
    uint32_t off = (uint32_t)tile * 32768u + laneoff + swz((uint32_t)row, kb);
    uint2 o2v;
    o2v.x = pack_h2(acc.x * sc, acc.y * sc);
    o2v.y = pack_h2(acc.z * sc, acc.w * sc);
    *(uint2*)(nimg + off) = o2v;
}

// ==================== HMMA dual GEMM, fp16 single-pass, 4x32KB phases ==============
__global__ void __launch_bounds__(256, 2)
gemm_hmma_kernel(const char* __restrict__ imgA, const char* __restrict__ imgN,
                 const char* __restrict__ Bs, const char* __restrict__ Bn,
                 const float* __restrict__ bias, float* __restrict__ out,
                 char* __restrict__ oImg, int relu, int write_img) {
    extern __shared__ char dyn_smem[];
    uint32_t sbase = (smem_u32(dyn_smem) + 127u) & ~127u;

    const int tid = threadIdx.x;
    const int wid = tid >> 5;
    const int lane = tid & 31;
    const int tile = blockIdx.x;
    const int m0 = tile * 128;
    const int wm = (wid >> 2) * 64;
    const int wn = (wid & 3) * 32;

    // 4 phases: p = part*2 + kc
    const char* srcA[4];
    const char* srcB[4];
    {
        const char* A0 = imgA + (size_t)tile * 32768;
        const char* N0 = imgN + (size_t)tile * 32768;
        #pragma unroll
        for (int kc = 0; kc < 2; ++kc) {
            srcA[kc] = A0 + kc * 16384;      srcB[kc] = Bs + kc * 16384;
            srcA[2 + kc] = N0 + kc * 16384;  srcB[2 + kc] = Bn + kc * 16384;
        }
    }

    auto stage = [&](int p, int b) {
        uint32_t sb = sbase + (uint32_t)b * 32768u;
        #pragma unroll
        for (int i = 0; i < 4; ++i) {
            uint32_t o = (uint32_t)(tid + i * 256) * 16u;
            cp_async16(sb + o, srcA[p] + o);
            cp_async16(sb + 16384 + o, srcB[p] + o);
        }
        CP_COMMIT();
    };

    float acc[4][4][4];
    #pragma unroll
    for (int i = 0; i < 4; i++)
        #pragma unroll
        for (int j = 0; j < 4; j++)
            #pragma unroll
            for (int r = 0; r < 4; r++) acc[i][j][r] = 0.f;

    stage(0, 0);

    #pragma unroll 1
    for (int p = 0; p < 4; ++p) {
        if (p < 3) { stage(p + 1, (p + 1) & 1); CP_WAIT(1); }
        else       { CP_WAIT(0); }
        __syncthreads();

        uint32_t sb = sbase + (uint32_t)(p & 1) * 32768u;
        const uint32_t sA = sb, sB = sb + 16384;
        #pragma unroll
        for (int ks = 0; ks < 4; ++ks) {
            uint32_t a[4][4];
            #pragma unroll
            for (int i = 0; i < 4; ++i) {
                uint32_t row = wm + i * 16 + (lane & 15);
                uint32_t kbyte = ks * 32 + ((lane >> 4) << 4);
                ldsm_x4(sA + swz(row, kbyte), a[i][0], a[i][1], a[i][2], a[i][3]);
            }
            uint32_t b[4][2];
            #pragma unroll
            for (int jj = 0; jj < 2; ++jj) {
                uint32_t mi = (uint32_t)lane >> 3;
                uint32_t row = wn + jj * 16 + ((mi >> 1) << 3) + (lane & 7);
                uint32_t kbyte = ks * 32 + ((mi & 1) << 4);
                uint32_t r0, r1, r2, r3;
                ldsm_x4(sB + swz(row, kbyte), r0, r1, r2, r3);
                b[jj * 2 + 0][0] = r0; b[jj * 2 + 0][1] = r1;
                b[jj * 2 + 1][0] = r2; b[jj * 2 + 1][1] = r3;
            }
            #pragma unroll
            for (int i = 0; i < 4; ++i)
                #pragma unroll
                for (int j = 0; j < 4; ++j)
                    mma_16816(acc[i][j], a[i], b[j]);
        }
        __syncthreads();   // all warps done reading buf before restage
    }

    // ---- epilogue: bias + relu; fp16 next-layer image OR final fp32 out ----
    #pragma unroll
    for (int i = 0; i < 4; ++i) {
        int rloc0 = wm + i * 16 + (lane >> 2);
        int r0 = m0 + rloc0;
        #pragma unroll
        for (int j = 0; j < 4; ++j) {
            int col = wn + j * 8 + (lane & 3) * 2;
            float bx = bias[col], by = bias[col + 1];
            float2 v0 = make_float2(acc[i][j][0] + bx, acc[i][j][1] + by);
            float2 v1 = make_float2(acc[i][j][2] + bx, acc[i][j][3] + by);
            if (relu) {
                v0.x = fmaxf(v0.x, 0.f); v0.y = fmaxf(v0.y, 0.f);
                v1.x = fmaxf(v1.x, 0.f); v1.y = fmaxf(v1.y, 0.f);
            }
            if (write_img) {
                uint32_t obase = (uint32_t)tile * 32768u + (uint32_t)(col >> 6) * 16384u;
                uint32_t kb = (uint32_t)((col & 63) * 2);
                if (r0 < N_NODES)
                    *(uint32_t*)(oImg + obase + swz((uint32_t)rloc0, kb)) = pack_h2(v0.x, v0.y);
                if (r0 + 8 < N_NODES)
                    *(uint32_t*)(oImg + obase + swz((uint32_t)(rloc0 + 8), kb)) = pack_h2(v1.x, v1.y);
            } else {
                if (r0 < N_NODES)
                    *reinterpret_cast<float2*>(out + (size_t)r0 * D + col) = v0;
                if (r0 + 8 < N_NODES)
                    *reinterpret_cast<float2*>(out + (size_t)(r0 + 8) * D + col) = v1;
            }
        }
    }
}

// ==================== launch ====================
extern "C" void kernel_launch(void* const* d_in, const int* in_sizes, int n_in,
                              void* d_out, int out_size) {
    const float* features = (const float*)d_in[0];
    const int* src = (const int*)d_in[1];
    const int* dst = (const int*)d_in[2];
    const float* Ws[3] = {(const float*)d_in[3], (const float*)d_in[6], (const float*)d_in[9]};
    const float* Wn[3] = {(const float*)d_in[4], (const float*)d_in[7], (const float*)d_in[10]};
    const float* bb[3] = {(const float*)d_in[5], (const float*)d_in[8], (const float*)d_in[11]};
    float* out = (float*)d_out;

    void *p_hist, *p_rank, *p_wimg, *p_img, *p_imgN;
    cudaGetSymbolAddress(&p_hist, g_hist);
    cudaGetSymbolAddress(&p_rank, g_rank);
    cudaGetSymbolAddress(&p_wimg, g_Wimg);
    cudaGetSymbolAddress(&p_img, g_img);
    cudaGetSymbolAddress(&p_imgN, g_imgN);

    char* wimg = (char*)p_wimg;
    auto wimgp = [&](int mat) { return wimg + (size_t)mat * 32768; };
    const size_t ISZ = (size_t)NT * 32768;   // bytes per h image
    char* himg = (char*)p_img;
    auto himgp = [&](int set) { return himg + (size_t)set * ISZ; };
    char* nimg = (char*)p_imgN;

    const size_t smem_bytes = 2 * 32768 + 128;
    cudaFuncSetAttribute(gemm_hmma_kernel, cudaFuncAttributeMaxDynamicSharedMemorySize,
                         (int)smem_bytes);

    cudaMemsetAsync(p_hist, 0, N_NODES * sizeof(int));
    hist_kernel<<<(N_EDGES / 4 + 255) / 256, 256>>>((const int4*)dst, (int4*)p_rank);
    convert_prep<<<NT + 48, 256>>>(features, himgp(0),
                                   Ws[0], Wn[0], Ws[1], Wn[1], Ws[2], Wn[2]);
    scan_local<<<SCAN_BLOCKS, 256>>>();
    scan_blocks<<<1, 256>>>();
    scan_apply<<<SCAN_BLOCKS, 256>>>();
    fill_kernel<<<(N_EDGES / 4 + 255) / 256, 256>>>((const int4*)src, (const int4*)dst,
                                                    (const int4*)p_rank);

    for (int l = 0; l < 3; ++l) {
        int rset = l & 1;            // 0,1,0
        int wset = 1 - rset;
        aggregate_kernel<<<(N_NODES * 32 + 255) / 256, 256>>>(himgp(rset), nimg);
        gemm_hmma_kernel<<<NT, 256, smem_bytes>>>(
            himgp(rset), nimg, wimgp(l * 2 + 0), wimgp(l * 2 + 1),
            bb[l], out, himgp(wset), (l < 2) ? 1 : 0, (l < 2) ? 1 : 0);
    }
}

// round 16
// speedup vs baseline: 1.0750x; 1.0188x over previous
#include <cuda_runtime.h>
#include <cuda_fp16.h>
#include <cstdint>

#define N_NODES 50000
#define N_EDGES 800000
#define D 128
#define NT 391            // ceil(N_NODES/128)
#define SCAN_BLOCKS 196   // 196*256 = 50176 >= N_NODES
#define HIST_BLOCKS 782   // ceil((N_EDGES/4)/256)

// ==================== scratch (no allocations allowed) ====================
__device__ int g_hist[N_NODES];
__device__ int g_rank[N_EDGES];
__device__ int g_rowstart[N_NODES + 1];
__device__ int g_col[N_EDGES];
__device__ int g_blocksum[SCAN_BLOCKS];
// fp16 swizzled weight images: [matrix 0..5][2 kchunks x 128 x 64]
__device__ __align__(128) __half g_Wimg[6][D * D];
// fp16 swizzled h tile images (ping-pong sets)
__device__ __align__(128) __half g_img[2][(size_t)NT * 16384];
// fp16 swizzled hneigh tile image
__device__ __align__(128) __half g_imgN[(size_t)NT * 16384];

// XOR swizzle: row-major 64 fp16 per row (128B), 8 chunks of 16B, chunk ^= row&7
__device__ __forceinline__ uint32_t swz(uint32_t row, uint32_t kbyte) {
    return row * 128u + ((((kbyte >> 4) ^ (row & 7u)) << 4) | (kbyte & 15u));
}

__device__ __forceinline__ uint32_t smem_u32(const void* p) {
    uint32_t a;
    asm("{ .reg .u64 t; cvta.to.shared.u64 t, %1; cvt.u32.u64 %0, t; }" : "=r"(a) : "l"(p));
    return a;
}
__device__ __forceinline__ void cp_async16(uint32_t saddr, const void* gptr) {
    asm volatile("cp.async.cg.shared.global [%0], [%1], 16;" :: "r"(saddr), "l"(gptr));
}
#define CP_COMMIT() asm volatile("cp.async.commit_group;" ::: "memory")
#define CP_WAIT(n)  asm volatile("cp.async.wait_group %0;" :: "n"(n) : "memory")

__device__ __forceinline__ void ldsm_x4(uint32_t addr, uint32_t& r0, uint32_t& r1,
                                        uint32_t& r2, uint32_t& r3) {
    asm volatile("ldmatrix.sync.aligned.m8n8.x4.shared.b16 {%0,%1,%2,%3}, [%4];"
                 : "=r"(r0), "=r"(r1), "=r"(r2), "=r"(r3) : "r"(addr));
}
__device__ __forceinline__ void mma_16816(float* c, const uint32_t* a, const uint32_t* b) {
    asm volatile(
        "mma.sync.aligned.m16n8k16.row.col.f32.f16.f16.f32 "
        "{%0,%1,%2,%3}, {%4,%5,%6,%7}, {%8,%9}, {%0,%1,%2,%3};"
        : "+f"(c[0]), "+f"(c[1]), "+f"(c[2]), "+f"(c[3])
        : "r"(a[0]), "r"(a[1]), "r"(a[2]), "r"(a[3]), "r"(b[0]), "r"(b[1]));
}
// 4 packed halves -> 4 floats
__device__ __forceinline__ float4 h4_to_f4(uint2 u) {
    __half2 a = *reinterpret_cast<__half2*>(&u.x);
    __half2 b = *reinterpret_cast<__half2*>(&u.y);
    float2 fa = __half22float2(a);
    float2 fb = __half22float2(b);
    return make_float4(fa.x, fa.y, fb.x, fb.y);
}
__device__ __forceinline__ uint32_t pack_h2(float x, float y) {
    __half2 h = __floats2half2_rn(x, y);
    return *reinterpret_cast<uint32_t*>(&h);
}

// ==================== merged preamble: convert + weight prep + hist/rank ==========
__global__ void convert_prep_hist(const float* __restrict__ h, char* __restrict__ img,
                                  const float* W0s, const float* W0n, const float* W1s,
                                  const float* W1n, const float* W2s, const float* W2n,
                                  const int4* __restrict__ dst4, int4* __restrict__ rank4) {
    if (blockIdx.x < NT) {
        int tile = blockIdx.x;
        int m0 = tile * 128;
        #pragma unroll 4
        for (int it = 0; it < 32; ++it) {
            int idx = threadIdx.x + it * 256;   // (row, kpair)
            int row = idx >> 6;
            int k = (idx & 63) * 2;
            int gm = m0 + row;
            float2 a = (gm < N_NODES) ? *reinterpret_cast<const float2*>(h + (size_t)gm * D + k)
                                      : make_float2(0.f, 0.f);
            uint32_t off = (uint32_t)tile * 32768u + (uint32_t)(k >> 6) * 16384u
                         + swz((uint32_t)row, (uint32_t)((k & 63) * 2));
            *(uint32_t*)(img + off) = pack_h2(a.x, a.y);
        }
    } else if (blockIdx.x < NT + 48) {
        const float* Wp[6] = {W0s, W0n, W1s, W1n, W2s, W2n};
        int b = blockIdx.x - NT;      // 0..47
        int mat = b >> 3;
        int sub = b & 7;
        const float* W = Wp[mat];
        char* wimg = (char*)g_Wimg[mat];
        for (int t = threadIdx.x; t < 1024; t += blockDim.x) {
            int idx = sub * 1024 + t;
            int n = idx >> 6;
            int k = (idx & 63) * 2;
            float a0 = W[(size_t)k * D + n];
            float a1 = W[(size_t)(k + 1) * D + n];
            uint32_t off = (uint32_t)(k >> 6) * 16384u
                         + swz((uint32_t)n, (uint32_t)((k & 63) * 2));
            *(uint32_t*)(wimg + off) = pack_h2(a0, a1);
        }
    } else {
        int i = (blockIdx.x - NT - 48) * 256 + threadIdx.x;
        if (i < N_EDGES / 4) {
            int4 d = dst4[i];
            int4 r;
            r.x = atomicAdd(&g_hist[d.x], 1);
            r.y = atomicAdd(&g_hist[d.y], 1);
            r.z = atomicAdd(&g_hist[d.z], 1);
            r.w = atomicAdd(&g_hist[d.w], 1);
            rank4[i] = r;
        }
    }
}

// ==================== scan (2 kernels) ====================
__global__ void scan_local() {
    __shared__ int sh[256];
    int t = threadIdx.x;
    int idx = blockIdx.x * 256 + t;
    int v = (idx < N_NODES) ? g_hist[idx] : 0;
    sh[t] = v;
    __syncthreads();
    #pragma unroll
    for (int off = 1; off < 256; off <<= 1) {
        int x = sh[t];
        int add = (t >= off) ? sh[t - off] : 0;
        __syncthreads();
        sh[t] = x + add;
        __syncthreads();
    }
    if (idx < N_NODES) g_rowstart[idx] = sh[t] - v;   // local exclusive
    if (t == 255) g_blocksum[blockIdx.x] = sh[255];
}

// every block redundantly scans the 196 block sums, then applies its offset
__global__ void scan_apply2() {
    __shared__ int sh[256];
    int t = threadIdx.x;
    int v = (t < SCAN_BLOCKS) ? g_blocksum[t] : 0;
    sh[t] = v;
    __syncthreads();
    #pragma unroll
    for (int off = 1; off < 256; off <<= 1) {
        int x = sh[t];
        int add = (t >= off) ? sh[t - off] : 0;
        __syncthreads();
        sh[t] = x + add;
        __syncthreads();
    }
    int boff = (blockIdx.x > 0) ? sh[blockIdx.x - 1] : 0;
    int idx = blockIdx.x * 256 + t;
    if (idx < N_NODES) g_rowstart[idx] += boff;
    if (blockIdx.x == SCAN_BLOCKS - 1 && t == 255)
        g_rowstart[N_NODES] = sh[SCAN_BLOCKS - 1];
}

// atomic-free fill: pos = rowstart[dst] + rank
__global__ void fill_kernel(const int4* __restrict__ src4, const int4* __restrict__ dst4,
                            const int4* __restrict__ rank4) {
    int i = blockIdx.x * blockDim.x + threadIdx.x;
    if (i < N_EDGES / 4) {
        int4 s = src4[i];
        int4 d = dst4[i];
        int4 r = rank4[i];
        g_col[g_rowstart[d.x] + r.x] = s.x;
        g_col[g_rowstart[d.y] + r.y] = s.y;
        g_col[g_rowstart[d.z] + r.z] = s.z;
        g_col[g_rowstart[d.w] + r.w] = s.w;
    }
}

// ==================== aggregation: warp/node, gathers fp16 image -> fp16 image =====
__global__ void aggregate_kernel(const char* __restrict__ img, char* __restrict__ nimg) {
    int node = (blockIdx.x * blockDim.x + threadIdx.x) >> 5;
    int lane = threadIdx.x & 31;
    if (node >= N_NODES) return;
    int beg = g_rowstart[node];
    int end = g_rowstart[node + 1];

    const int k0 = lane * 4;                                  // features k0..k0+3
    const uint32_t laneoff = (uint32_t)(k0 >> 6) * 16384u;    // k-chunk select
    const uint32_t kb = (uint32_t)((k0 & 63) * 2);            // byte within row

    float4 acc = make_float4(0.f, 0.f, 0.f, 0.f);
    int i = beg;
    for (; i + 4 <= end; i += 4) {
        int s0 = g_col[i + 0];
        int s1 = g_col[i + 1];
        int s2 = g_col[i + 2];
        int s3 = g_col[i + 3];
        uint32_t o0 = (uint32_t)(s0 >> 7) * 32768u + laneoff + swz((uint32_t)(s0 & 127), kb);
        uint32_t o1 = (uint32_t)(s1 >> 7) * 32768u + laneoff + swz((uint32_t)(s1 & 127), kb);
        uint32_t o2 = (uint32_t)(s2 >> 7) * 32768u + laneoff + swz((uint32_t)(s2 & 127), kb);
        uint32_t o3 = (uint32_t)(s3 >> 7) * 32768u + laneoff + swz((uint32_t)(s3 & 127), kb);
        float4 v0 = h4_to_f4(*(const uint2*)(img + o0));
        float4 v1 = h4_to_f4(*(const uint2*)(img + o1));
        float4 v2 = h4_to_f4(*(const uint2*)(img + o2));
        float4 v3 = h4_to_f4(*(const uint2*)(img + o3));
        acc.x += (v0.x + v1.x) + (v2.x + v3.x);
        acc.y += (v0.y + v1.y) + (v2.y + v3.y);
        acc.z += (v0.z + v1.z) + (v2.z + v3.z);
        acc.w += (v0.w + v1.w) + (v2.w + v3.w);
    }
    for (; i < end; ++i) {
        int s = g_col[i];
        uint32_t o = (uint32_t)(s >> 7) * 32768u + laneoff + swz((uint32_t)(s & 127), kb);
        float4 v = h4_to_f4(*(const uint2*)(img + o));
        acc.x += v.x; acc.y += v.y; acc.z += v.z; acc.w += v.w;
    }
    float sc = 1.0f / fmaxf((float)(end - beg), 1.0f);

    int tile = node >> 7;
    int row = node & 127;
    uint32_t off = (uint32_t)tile * 32768u + laneoff + swz((uint32_t)row, kb);
    uint2 o2v;
    o2v.x = pack_h2(acc.x * sc, acc.y * sc);
    o2v.y = pack_h2(acc.z * sc, acc.w * sc);
    *(uint2*)(nimg + off) = o2v;
}

// ==================== HMMA dual GEMM, fp16, 4 phases, 3-buffer rotation ============
__global__ void __launch_bounds__(256, 2)
gemm_hmma_kernel(const char* __restrict__ imgA, const char* __restrict__ imgN,
                 const char* __restrict__ Bs, const char* __restrict__ Bn,
                 const float* __restrict__ bias, float* __restrict__ out,
                 char* __restrict__ oImg, int relu, int write_img) {
    extern __shared__ char dyn_smem[];
    uint32_t sbase = (smem_u32(dyn_smem) + 127u) & ~127u;

    const int tid = threadIdx.x;
    const int wid = tid >> 5;
    const int lane = tid & 31;
    const int tile = blockIdx.x;
    const int m0 = tile * 128;
    const int wm = (wid >> 2) * 64;
    const int wn = (wid & 3) * 32;

    // 4 phases: p = part*2 + kc
    const char* srcA[4];
    const char* srcB[4];
    {
        const char* A0 = imgA + (size_t)tile * 32768;
        const char* N0 = imgN + (size_t)tile * 32768;
        #pragma unroll
        for (int kc = 0; kc < 2; ++kc) {
            srcA[kc] = A0 + kc * 16384;      srcB[kc] = Bs + kc * 16384;
            srcA[2 + kc] = N0 + kc * 16384;  srcB[2 + kc] = Bn + kc * 16384;
        }
    }

    auto stage = [&](int p, int b) {
        uint32_t sb = sbase + (uint32_t)b * 32768u;
        #pragma unroll
        for (int i = 0; i < 4; ++i) {
            uint32_t o = (uint32_t)(tid + i * 256) * 16u;
            cp_async16(sb + o, srcA[p] + o);
            cp_async16(sb + 16384 + o, srcB[p] + o);
        }
        CP_COMMIT();
    };

    float acc[4][4][4];
    #pragma unroll
    for (int i = 0; i < 4; i++)
        #pragma unroll
        for (int j = 0; j < 4; j++)
            #pragma unroll
            for (int r = 0; r < 4; r++) acc[i][j][r] = 0.f;

    stage(0, 0);

    #pragma unroll 1
    for (int p = 0; p < 4; ++p) {
        if (p < 3) { stage(p + 1, (p + 1) % 3); CP_WAIT(1); }
        else       { CP_WAIT(0); }
        __syncthreads();   // buffer p%3 complete for all warps

        uint32_t sb = sbase + (uint32_t)(p % 3) * 32768u;
        const uint32_t sA = sb, sB = sb + 16384;
        #pragma unroll
        for (int ks = 0; ks < 4; ++ks) {
            uint32_t a[4][4];
            #pragma unroll
            for (int i = 0; i < 4; ++i) {
                uint32_t row = wm + i * 16 + (lane & 15);
                uint32_t kbyte = ks * 32 + ((lane >> 4) << 4);
                ldsm_x4(sA + swz(row, kbyte), a[i][0], a[i][1], a[i][2], a[i][3]);
            }
            uint32_t b[4][2];
            #pragma unroll
            for (int jj = 0; jj < 2; ++jj) {
                uint32_t mi = (uint32_t)lane >> 3;
                uint32_t row = wn + jj * 16 + ((mi >> 1) << 3) + (lane & 7);
                uint32_t kbyte = ks * 32 + ((mi & 1) << 4);
                uint32_t r0, r1, r2, r3;
                ldsm_x4(sB + swz(row, kbyte), r0, r1, r2, r3);
                b[jj * 2 + 0][0] = r0; b[jj * 2 + 0][1] = r1;
                b[jj * 2 + 1][0] = r2; b[jj * 2 + 1][1] = r3;
            }
            #pragma unroll
            for (int i = 0; i < 4; ++i)
                #pragma unroll
                for (int j = 0; j < 4; ++j)
                    mma_16816(acc[i][j], a[i], b[j]);
        }
        // no trailing sync: next restage of this buffer is >=3 phases away,
        // separated by two head-of-loop barriers.
    }

    // ---- epilogue: bias + relu; fp16 next-layer image OR final fp32 out ----
    #pragma unroll
    for (int i = 0; i < 4; ++i) {
        int rloc0 = wm + i * 16 + (lane >> 2);
        int r0 = m0 + rloc0;
        #pragma unroll
        for (int j = 0; j < 4; ++j) {
            int col = wn + j * 8 + (lane & 3) * 2;
            float bx = bias[col], by = bias[col + 1];
            float2 v0 = make_float2(acc[i][j][0] + bx, acc[i][j][1] + by);
            float2 v1 = make_float2(acc[i][j][2] + bx, acc[i][j][3] + by);
            if (relu) {
                v0.x = fmaxf(v0.x, 0.f); v0.y = fmaxf(v0.y, 0.f);
                v1.x = fmaxf(v1.x, 0.f); v1.y = fmaxf(v1.y, 0.f);
            }
            if (write_img) {
                uint32_t obase = (uint32_t)tile * 32768u + (uint32_t)(col >> 6) * 16384u;
                uint32_t kb = (uint32_t)((col & 63) * 2);
                if (r0 < N_NODES)
                    *(uint32_t*)(oImg + obase + swz((uint32_t)rloc0, kb)) = pack_h2(v0.x, v0.y);
                if (r0 + 8 < N_NODES)
                    *(uint32_t*)(oImg + obase + swz((uint32_t)(rloc0 + 8), kb)) = pack_h2(v1.x, v1.y);
            } else {
                if (r0 < N_NODES)
                    *reinterpret_cast<float2*>(out + (size_t)r0 * D + col) = v0;
                if (r0 + 8 < N_NODES)
                    *reinterpret_cast<float2*>(out + (size_t)(r0 + 8) * D + col) = v1;
            }
        }
    }
}

// ==================== launch ====================
extern "C" void kernel_launch(void* const* d_in, const int* in_sizes, int n_in,
                              void* d_out, int out_size) {
    const float* features = (const float*)d_in[0];
    const int* src = (const int*)d_in[1];
    const int* dst = (const int*)d_in[2];
    const float* Ws[3] = {(const float*)d_in[3], (const float*)d_in[6], (const float*)d_in[9]};
    const float* Wn[3] = {(const float*)d_in[4], (const float*)d_in[7], (const float*)d_in[10]};
    const float* bb[3] = {(const float*)d_in[5], (const float*)d_in[8], (const float*)d_in[11]};
    float* out = (float*)d_out;

    void *p_hist, *p_rank, *p_wimg, *p_img, *p_imgN;
    cudaGetSymbolAddress(&p_hist, g_hist);
    cudaGetSymbolAddress(&p_rank, g_rank);
    cudaGetSymbolAddress(&p_wimg, g_Wimg);
    cudaGetSymbolAddress(&p_img, g_img);
    cudaGetSymbolAddress(&p_imgN, g_imgN);

    char* wimg = (char*)p_wimg;
    auto wimgp = [&](int mat) { return wimg + (size_t)mat * 32768; };
    const size_t ISZ = (size_t)NT * 32768;   // bytes per h image
    char* himg = (char*)p_img;
    auto himgp = [&](int set) { return himg + (size_t)set * ISZ; };
    char* nimg = (char*)p_imgN;

    const size_t smem_bytes = 3 * 32768 + 128;
    cudaFuncSetAttribute(gemm_hmma_kernel, cudaFuncAttributeMaxDynamicSharedMemorySize,
                         (int)smem_bytes);

    cudaMemsetAsync(p_hist, 0, N_NODES * sizeof(int));
    convert_prep_hist<<<NT + 48 + HIST_BLOCKS, 256>>>(
        features, himgp(0), Ws[0], Wn[0], Ws[1], Wn[1], Ws[2], Wn[2],
        (const int4*)dst, (int4*)p_rank);
    scan_local<<<SCAN_BLOCKS, 256>>>();
    scan_apply2<<<SCAN_BLOCKS, 256>>>();
    fill_kernel<<<(N_EDGES / 4 + 255) / 256, 256>>>((const int4*)src, (const int4*)dst,
                                                    (const int4*)p_rank);

    for (int l = 0; l < 3; ++l) {
        int rset = l & 1;            // 0,1,0
        int wset = 1 - rset;
        aggregate_kernel<<<(N_NODES * 32 + 255) / 256, 256>>>(himgp(rset), nimg);
        gemm_hmma_kernel<<<NT, 256, smem_bytes>>>(
            himgp(rset), nimg, wimgp(l * 2 + 0), wimgp(l * 2 + 1),
            bb[l], out, himgp(wset), (l < 2) ? 1 : 0, (l < 2) ? 1 : 0);
    }
}

// round 17
// speedup vs baseline: 1.0827x; 1.0072x over previous
#include <cuda_runtime.h>
#include <cuda_fp16.h>
#include <cstdint>

#define N_NODES 50000
#define N_EDGES 800000
#define D 128
#define NT 391            // ceil(N_NODES/128)
#define SCAN_BLOCKS 196   // 196*256 = 50176 >= N_NODES
#define HIST_BLOCKS 782   // ceil((N_EDGES/4)/256)

// ==================== scratch (no allocations allowed) ====================
__device__ int g_hist[N_NODES];
__device__ int g_rank[N_EDGES];
__device__ int g_rowstart[N_NODES + 1];
__device__ int g_col[N_EDGES];
__device__ int g_blocksum[SCAN_BLOCKS];
// fp16 swizzled weight images: [matrix 0..5][2 kchunks x 128 x 64]
__device__ __align__(128) __half g_Wimg[6][D * D];
// fp16 swizzled h tile images (ping-pong sets)
__device__ __align__(128) __half g_img[2][(size_t)NT * 16384];
// fp16 swizzled hneigh tile image
__device__ __align__(128) __half g_imgN[(size_t)NT * 16384];

// XOR swizzle: row-major 64 fp16 per row (128B), 8 chunks of 16B, chunk ^= row&7
__device__ __forceinline__ uint32_t swz(uint32_t row, uint32_t kbyte) {
    return row * 128u + ((((kbyte >> 4) ^ (row & 7u)) << 4) | (kbyte & 15u));
}

__device__ __forceinline__ uint32_t smem_u32(const void* p) {
    uint32_t a;
    asm("{ .reg .u64 t; cvta.to.shared.u64 t, %1; cvt.u32.u64 %0, t; }" : "=r"(a) : "l"(p));
    return a;
}
__device__ __forceinline__ void cp_async16(uint32_t saddr, const void* gptr) {
    asm volatile("cp.async.cg.shared.global [%0], [%1], 16;" :: "r"(saddr), "l"(gptr));
}
#define CP_COMMIT() asm volatile("cp.async.commit_group;" ::: "memory")
#define CP_WAIT(n)  asm volatile("cp.async.wait_group %0;" :: "n"(n) : "memory")

__device__ __forceinline__ void ldsm_x4(uint32_t addr, uint32_t& r0, uint32_t& r1,
                                        uint32_t& r2, uint32_t& r3) {
    asm volatile("ldmatrix.sync.aligned.m8n8.x4.shared.b16 {%0,%1,%2,%3}, [%4];"
                 : "=r"(r0), "=r"(r1), "=r"(r2), "=r"(r3) : "r"(addr));
}
__device__ __forceinline__ void mma_16816(float* c, const uint32_t* a, const uint32_t* b) {
    asm volatile(
        "mma.sync.aligned.m16n8k16.row.col.f32.f16.f16.f32 "
        "{%0,%1,%2,%3}, {%4,%5,%6,%7}, {%8,%9}, {%0,%1,%2,%3};"
        : "+f"(c[0]), "+f"(c[1]), "+f"(c[2]), "+f"(c[3])
        : "r"(a[0]), "r"(a[1]), "r"(a[2]), "r"(a[3]), "r"(b[0]), "r"(b[1]));
}
// 4 packed halves -> 4 floats
__device__ __forceinline__ float4 h4_to_f4(uint2 u) {
    __half2 a = *reinterpret_cast<__half2*>(&u.x);
    __half2 b = *reinterpret_cast<__half2*>(&u.y);
    float2 fa = __half22float2(a);
    float2 fb = __half22float2(b);
    return make_float4(fa.x, fa.y, fb.x, fb.y);
}
__device__ __forceinline__ uint32_t pack_h2(float x, float y) {
    __half2 h = __floats2half2_rn(x, y);
    return *reinterpret_cast<uint32_t*>(&h);
}
// warp-inclusive scan of int via shfl
__device__ __forceinline__ int warp_iscan(int x, int lane) {
    #pragma unroll
    for (int off = 1; off < 32; off <<= 1) {
        int n = __shfl_up_sync(0xffffffffu, x, off);
        if (lane >= off) x += n;
    }
    return x;
}

// ==================== merged preamble: convert + weight prep + hist/rank ==========
__global__ void convert_prep_hist(const float* __restrict__ h, char* __restrict__ img,
                                  const float* W0s, const float* W0n, const float* W1s,
                                  const float* W1n, const float* W2s, const float* W2n,
                                  const int4* __restrict__ dst4, int4* __restrict__ rank4) {
    if (blockIdx.x < NT) {
        int tile = blockIdx.x;
        int m0 = tile * 128;
        #pragma unroll 4
        for (int it = 0; it < 32; ++it) {
            int idx = threadIdx.x + it * 256;   // (row, kpair)
            int row = idx >> 6;
            int k = (idx & 63) * 2;
            int gm = m0 + row;
            float2 a = (gm < N_NODES) ? *reinterpret_cast<const float2*>(h + (size_t)gm * D + k)
                                      : make_float2(0.f, 0.f);
            uint32_t off = (uint32_t)tile * 32768u + (uint32_t)(k >> 6) * 16384u
                         + swz((uint32_t)row, (uint32_t)((k & 63) * 2));
            *(uint32_t*)(img + off) = pack_h2(a.x, a.y);
        }
    } else if (blockIdx.x < NT + 48) {
        const float* Wp[6] = {W0s, W0n, W1s, W1n, W2s, W2n};
        int b = blockIdx.x - NT;      // 0..47
        int mat = b >> 3;
        int sub = b & 7;
        const float* W = Wp[mat];
        char* wimg = (char*)g_Wimg[mat];
        for (int t = threadIdx.x; t < 1024; t += blockDim.x) {
            int idx = sub * 1024 + t;
            int n = idx >> 6;
            int k = (idx & 63) * 2;
            float a0 = W[(size_t)k * D + n];
            float a1 = W[(size_t)(k + 1) * D + n];
            uint32_t off = (uint32_t)(k >> 6) * 16384u
                         + swz((uint32_t)n, (uint32_t)((k & 63) * 2));
            *(uint32_t*)(wimg + off) = pack_h2(a0, a1);
        }
    } else {
        int i = (blockIdx.x - NT - 48) * 256 + threadIdx.x;
        if (i < N_EDGES / 4) {
            int4 d = dst4[i];
            int4 r;
            r.x = atomicAdd(&g_hist[d.x], 1);
            r.y = atomicAdd(&g_hist[d.y], 1);
            r.z = atomicAdd(&g_hist[d.z], 1);
            r.w = atomicAdd(&g_hist[d.w], 1);
            rank4[i] = r;
        }
    }
}

// ==================== scan (2 kernels, shuffle-based) ====================
__global__ void scan_local() {
    __shared__ int wsum[8];
    __shared__ int woff[8];
    int t = threadIdx.x;
    int lane = t & 31;
    int w = t >> 5;
    int idx = blockIdx.x * 256 + t;
    int v = (idx < N_NODES) ? g_hist[idx] : 0;
    int incl = warp_iscan(v, lane);
    if (lane == 31) wsum[w] = incl;
    __syncthreads();
    if (w == 0) {
        int x = (lane < 8) ? wsum[lane] : 0;
        int s = warp_iscan(x, lane);
        if (lane < 8) woff[lane] = s - x;    // exclusive warp offset
    }
    __syncthreads();
    int ex = woff[w] + incl - v;
    if (idx < N_NODES) g_rowstart[idx] = ex;         // local exclusive
    if (t == 255) g_blocksum[blockIdx.x] = woff[7] + wsum[7];
}

// every block redundantly scans the 196 block sums, then applies its offset
__global__ void scan_apply2() {
    __shared__ int wsum[8];
    __shared__ int woff[8];
    int t = threadIdx.x;
    int lane = t & 31;
    int w = t >> 5;
    int v = (t < SCAN_BLOCKS) ? g_blocksum[t] : 0;
    int incl = warp_iscan(v, lane);
    if (lane == 31) wsum[w] = incl;
    __syncthreads();
    if (w == 0) {
        int x = (lane < 8) ? wsum[lane] : 0;
        int s = warp_iscan(x, lane);
        if (lane < 8) woff[lane] = s - x;
    }
    __syncthreads();
    int incl_g = woff[w] + incl;             // global inclusive of blocksum[t]
    // need exclusive prefix of blocksum for block b = inclusive[b-1]
    __shared__ int s_all[256];
    s_all[t] = incl_g;
    __syncthreads();
    int boff = (blockIdx.x > 0) ? s_all[blockIdx.x - 1] : 0;
    int idx = blockIdx.x * 256 + t;
    if (idx < N_NODES) g_rowstart[idx] += boff;
    if (blockIdx.x == SCAN_BLOCKS - 1 && t == 255)
        g_rowstart[N_NODES] = s_all[SCAN_BLOCKS - 1];
}

// atomic-free fill: pos = rowstart[dst] + rank, 8 edges per thread
__global__ void fill_kernel(const int4* __restrict__ src4, const int4* __restrict__ dst4,
                            const int4* __restrict__ rank4) {
    int i = (blockIdx.x * blockDim.x + threadIdx.x) * 2;
    if (i + 1 < N_EDGES / 4) {
        int4 s0 = src4[i],   s1 = src4[i + 1];
        int4 d0 = dst4[i],   d1 = dst4[i + 1];
        int4 r0 = rank4[i],  r1 = rank4[i + 1];
        int p0 = g_rowstart[d0.x] + r0.x;
        int p1 = g_rowstart[d0.y] + r0.y;
        int p2 = g_rowstart[d0.z] + r0.z;
        int p3 = g_rowstart[d0.w] + r0.w;
        int p4 = g_rowstart[d1.x] + r1.x;
        int p5 = g_rowstart[d1.y] + r1.y;
        int p6 = g_rowstart[d1.z] + r1.z;
        int p7 = g_rowstart[d1.w] + r1.w;
        g_col[p0] = s0.x; g_col[p1] = s0.y; g_col[p2] = s0.z; g_col[p3] = s0.w;
        g_col[p4] = s1.x; g_col[p5] = s1.y; g_col[p6] = s1.z; g_col[p7] = s1.w;
    } else if (i < N_EDGES / 4) {
        int4 s = src4[i];
        int4 d = dst4[i];
        int4 r = rank4[i];
        g_col[g_rowstart[d.x] + r.x] = s.x;
        g_col[g_rowstart[d.y] + r.y] = s.y;
        g_col[g_rowstart[d.z] + r.z] = s.z;
        g_col[g_rowstart[d.w] + r.w] = s.w;
    }
}

// ==================== aggregation: warp/node, gathers fp16 image -> fp16 image =====
__global__ void aggregate_kernel(const char* __restrict__ img, char* __restrict__ nimg) {
    int node = (blockIdx.x * blockDim.x + threadIdx.x) >> 5;
    int lane = threadIdx.x & 31;
    if (node >= N_NODES) return;
    int beg = g_rowstart[node];
    int end = g_rowstart[node + 1];

    const int k0 = lane * 4;                                  // features k0..k0+3
    const uint32_t laneoff = (uint32_t)(k0 >> 6) * 16384u;    // k-chunk select
    const uint32_t kb = (uint32_t)((k0 & 63) * 2);            // byte within row

    float4 acc = make_float4(0.f, 0.f, 0.f, 0.f);
    int i = beg;
    for (; i + 4 <= end; i += 4) {
        int s0 = g_col[i + 0];
        int s1 = g_col[i + 1];
        int s2 = g_col[i + 2];
        int s3 = g_col[i + 3];
        uint32_t o0 = (uint32_t)(s0 >> 7) * 32768u + laneoff + swz((uint32_t)(s0 & 127), kb);
        uint32_t o1 = (uint32_t)(s1 >> 7) * 32768u + laneoff + swz((uint32_t)(s1 & 127), kb);
        uint32_t o2 = (uint32_t)(s2 >> 7) * 32768u + laneoff + swz((uint32_t)(s2 & 127), kb);
        uint32_t o3 = (uint32_t)(s3 >> 7) * 32768u + laneoff + swz((uint32_t)(s3 & 127), kb);
        float4 v0 = h4_to_f4(*(const uint2*)(img + o0));
        float4 v1 = h4_to_f4(*(const uint2*)(img + o1));
        float4 v2 = h4_to_f4(*(const uint2*)(img + o2));
        float4 v3 = h4_to_f4(*(const uint2*)(img + o3));
        acc.x += (v0.x + v1.x) + (v2.x + v3.x);
        acc.y += (v0.y + v1.y) + (v2.y + v3.y);
        acc.z += (v0.z + v1.z) + (v2.z + v3.z);
        acc.w += (v0.w + v1.w) + (v2.w + v3.w);
    }
    for (; i < end; ++i) {
        int s = g_col[i];
        uint32_t o = (uint32_t)(s >> 7) * 32768u + laneoff + swz((uint32_t)(s & 127), kb);
        float4 v = h4_to_f4(*(const uint2*)(img + o));
        acc.x += v.x; acc.y += v.y; acc.z += v.z; acc.w += v.w;
    }
    float sc = 1.0f / fmaxf((float)(end - beg), 1.0f);

    int tile = node >> 7;
    int row = node & 127;
    uint32_t off = (uint32_t)tile * 32768u + laneoff + swz((uint32_t)row, kb);
    uint2 o2v;
    o2v.x = pack_h2(acc.x * sc, acc.y * sc);
    o2v.y = pack_h2(acc.z * sc, acc.w * sc);
    *(uint2*)(nimg + off) = o2v;
}

// ==================== HMMA dual GEMM, fp16, 4 phases, 3-buffer rotation ============
__global__ void __launch_bounds__(256, 2)
gemm_hmma_kernel(const char* __restrict__ imgA, const char* __restrict__ imgN,
                 const char* __restrict__ Bs, const char* __restrict__ Bn,
                 const float* __restrict__ bias, float* __restrict__ out,
                 char* __restrict__ oImg, int relu, int write_img) {
    extern __shared__ char dyn_smem[];
    uint32_t sbase = (smem_u32(dyn_smem) + 127u) & ~127u;

    const int tid = threadIdx.x;
    const int wid = tid >> 5;
    const int lane = tid & 31;
    const int tile = blockIdx.x;
    const int m0 = tile * 128;
    const int wm = (wid >> 2) * 64;
    const int wn = (wid & 3) * 32;

    // 4 phases: p = part*2 + kc
    const char* srcA[4];
    const char* srcB[4];
    {
        const char* A0 = imgA + (size_t)tile * 32768;
        const char* N0 = imgN + (size_t)tile * 32768;
        #pragma unroll
        for (int kc = 0; kc < 2; ++kc) {
            srcA[kc] = A0 + kc * 16384;      srcB[kc] = Bs + kc * 16384;
            srcA[2 + kc] = N0 + kc * 16384;  srcB[2 + kc] = Bn + kc * 16384;
        }
    }

    auto stage = [&](int p, int b) {
        uint32_t sb = sbase + (uint32_t)b * 32768u;
        #pragma unroll
        for (int i = 0; i < 4; ++i) {
            uint32_t o = (uint32_t)(tid + i * 256) * 16u;
            cp_async16(sb + o, srcA[p] + o);
            cp_async16(sb + 16384 + o, srcB[p] + o);
        }
        CP_COMMIT();
    };

    float acc[4][4][4];
    #pragma unroll
    for (int i = 0; i < 4; i++)
        #pragma unroll
        for (int j = 0; j < 4; j++)
            #pragma unroll
            for (int r = 0; r < 4; r++) acc[i][j][r] = 0.f;

    stage(0, 0);

    #pragma unroll 1
    for (int p = 0; p < 4; ++p) {
        if (p < 3) { stage(p + 1, (p + 1) % 3); CP_WAIT(1); }
        else       { CP_WAIT(0); }
        __syncthreads();   // buffer p%3 complete for all warps

        uint32_t sb = sbase + (uint32_t)(p % 3) * 32768u;
        const uint32_t sA = sb, sB = sb + 16384;
        #pragma unroll
        for (int ks = 0; ks < 4; ++ks) {
            uint32_t a[4][4];
            #pragma unroll
            for (int i = 0; i < 4; ++i) {
                uint32_t row = wm + i * 16 + (lane & 15);
                uint32_t kbyte = ks * 32 + ((lane >> 4) << 4);
                ldsm_x4(sA + swz(row, kbyte), a[i][0], a[i][1], a[i][2], a[i][3]);
            }
            uint32_t b[4][2];
            #pragma unroll
            for (int jj = 0; jj < 2; ++jj) {
                uint32_t mi = (uint32_t)lane >> 3;
                uint32_t row = wn + jj * 16 + ((mi >> 1) << 3) + (lane & 7);
                uint32_t kbyte = ks * 32 + ((mi & 1) << 4);
                uint32_t r0, r1, r2, r3;
                ldsm_x4(sB + swz(row, kbyte), r0, r1, r2, r3);
                b[jj * 2 + 0][0] = r0; b[jj * 2 + 0][1] = r1;
                b[jj * 2 + 1][0] = r2; b[jj * 2 + 1][1] = r3;
            }
            #pragma unroll
            for (int i = 0; i < 4; ++i)
                #pragma unroll
                for (int j = 0; j < 4; ++j)
                    mma_16816(acc[i][j], a[i], b[j]);
        }
        // no trailing sync: this buffer is restaged >=3 phases later,
        // separated by two head-of-loop barriers.
    }

    // ---- epilogue: bias + relu; fp16 next-layer image OR final fp32 out ----
    #pragma unroll
    for (int i = 0; i < 4; ++i) {
        int rloc0 = wm + i * 16 + (lane >> 2);
        int r0 = m0 + rloc0;
        #pragma unroll
        for (int j = 0; j < 4; ++j) {
            int col = wn + j * 8 + (lane & 3) * 2;
            float bx = bias[col], by = bias[col + 1];
            float2 v0 = make_float2(acc[i][j][0] + bx, acc[i][j][1] + by);
            float2 v1 = make_float2(acc[i][j][2] + bx, acc[i][j][3] + by);
            if (relu) {
                v0.x = fmaxf(v0.x, 0.f); v0.y = fmaxf(v0.y, 0.f);
                v1.x = fmaxf(v1.x, 0.f); v1.y = fmaxf(v1.y, 0.f);
            }
            if (write_img) {
                uint32_t obase = (uint32_t)tile * 32768u + (uint32_t)(col >> 6) * 16384u;
                uint32_t kb = (uint32_t)((col & 63) * 2);
                if (r0 < N_NODES)
                    *(uint32_t*)(oImg + obase + swz((uint32_t)rloc0, kb)) = pack_h2(v0.x, v0.y);
                if (r0 + 8 < N_NODES)
                    *(uint32_t*)(oImg + obase + swz((uint32_t)(rloc0 + 8), kb)) = pack_h2(v1.x, v1.y);
            } else {
                if (r0 < N_NODES)
                    *reinterpret_cast<float2*>(out + (size_t)r0 * D + col) = v0;
                if (r0 + 8 < N_NODES)
                    *reinterpret_cast<float2*>(out + (size_t)(r0 + 8) * D + col) = v1;
            }
        }
    }
}

// ==================== launch ====================
extern "C" void kernel_launch(void* const* d_in, const int* in_sizes, int n_in,
                              void* d_out, int out_size) {
    const float* features = (const float*)d_in[0];
    const int* src = (const int*)d_in[1];
    const int* dst = (const int*)d_in[2];
    const float* Ws[3] = {(const float*)d_in[3], (const float*)d_in[6], (const float*)d_in[9]};
    const float* Wn[3] = {(const float*)d_in[4], (const float*)d_in[7], (const float*)d_in[10]};
    const float* bb[3] = {(const float*)d_in[5], (const float*)d_in[8], (const float*)d_in[11]};
    float* out = (float*)d_out;

    void *p_hist, *p_rank, *p_wimg, *p_img, *p_imgN;
    cudaGetSymbolAddress(&p_hist, g_hist);
    cudaGetSymbolAddress(&p_rank, g_rank);
    cudaGetSymbolAddress(&p_wimg, g_Wimg);
    cudaGetSymbolAddress(&p_img, g_img);
    cudaGetSymbolAddress(&p_imgN, g_imgN);

    char* wimg = (char*)p_wimg;
    auto wimgp = [&](int mat) { return wimg + (size_t)mat * 32768; };
    const size_t ISZ = (size_t)NT * 32768;   // bytes per h image
    char* himg = (char*)p_img;
    auto himgp = [&](int set) { return himg + (size_t)set * ISZ; };
    char* nimg = (char*)p_imgN;

    const size_t smem_bytes = 3 * 32768 + 128;
    cudaFuncSetAttribute(gemm_hmma_kernel, cudaFuncAttributeMaxDynamicSharedMemorySize,
                         (int)smem_bytes);

    cudaMemsetAsync(p_hist, 0, N_NODES * sizeof(int));
    convert_prep_hist<<<NT + 48 + HIST_BLOCKS, 256>>>(
        features, himgp(0), Ws[0], Wn[0], Ws[1], Wn[1], Ws[2], Wn[2],
        (const int4*)dst, (int4*)p_rank);
    scan_local<<<SCAN_BLOCKS, 256>>>();
    scan_apply2<<<SCAN_BLOCKS, 256>>>();
    fill_kernel<<<(N_EDGES / 8 + 255) / 256, 256>>>((const int4*)src, (const int4*)dst,
                                                    (const int4*)p_rank);

    for (int l = 0; l < 3; ++l) {
        int rset = l & 1;            // 0,1,0
        int wset = 1 - rset;
        aggregate_kernel<<<(N_NODES * 32 + 255) / 256, 256>>>(himgp(rset), nimg);
        gemm_hmma_kernel<<<NT, 256, smem_bytes>>>(
            himgp(rset), nimg, wimgp(l * 2 + 0), wimgp(l * 2 + 1),
            bb[l], out, himgp(wset), (l < 2) ? 1 : 0, (l < 2) ? 1 : 0);
    }
}